// round 11
// baseline (speedup 1.0000x reference)
#include <cuda_runtime.h>

#define T_LEN   2048
#define BATCH   16
#define NFREQ   1152
#define NOCT    9
#define NF0     128

typedef unsigned long long u64;

// -------- device scratch --------
__device__ float g_mag[BATCH * NFREQ];
__device__ int   g_cnt[BATCH];            // zero-init; self-resetting each launch

// -------- packed f32x2 helpers --------
__device__ __forceinline__ u64 pk(float lo, float hi) {
    u64 r; asm("mov.b64 %0,{%1,%2};" : "=l"(r) : "f"(lo), "f"(hi)); return r;
}
__device__ __forceinline__ void upk(u64 v, float& lo, float& hi) {
    asm("mov.b64 {%0,%1},%2;" : "=f"(lo), "=f"(hi) : "l"(v));
}
__device__ __forceinline__ u64 bc2(float v) {
    unsigned u = __float_as_uint(v);
    return (u64)u | ((u64)u << 32);
}
__device__ __forceinline__ u64 fma2(u64 a, u64 b, u64 c) {
    u64 d; asm("fma.rn.f32x2 %0,%1,%2,%3;" : "=l"(d) : "l"(a), "l"(b), "l"(c)); return d;
}
__device__ __forceinline__ u64 mul2(u64 a, u64 b) {
    u64 d; asm("mul.rn.f32x2 %0,%1,%2;" : "=l"(d) : "l"(a), "l"(b)); return d;
}
__device__ __forceinline__ u64 add2(u64 a, u64 b) {
    u64 d; asm("add.rn.f32x2 %0,%1,%2;" : "=l"(d) : "l"(a), "l"(b)); return d;
}
__device__ __forceinline__ u64 sub2(u64 a, u64 b) {
    u64 d; asm("sub.rn.f32x2 %0,%1,%2;" : "=l"(d) : "l"(a), "l"(b)); return d;
}
__device__ __forceinline__ float mufu_sin(float x) {
    float r; asm("sin.approx.f32 %0, %1;" : "=f"(r) : "f"(x)); return r;
}
__device__ __forceinline__ float mufu_cos(float x) {
    float r; asm("cos.approx.f32 %0, %1;" : "=f"(r) : "f"(x)); return r;
}

// One packed pair of time steps across 9 octaves.
// Base sin/cos via MUFU (idle pipe); Chebyshev recurrence on v = 2cos:
//   v' = v*v - 2, s' = s*v   (2 FMA-pipe ops/octave)
// A2 accumulates yn*v == 2*(y*cos); factor 2 removed once in the epilogue.
#define EVAL_PAIR(tv, yn)                                                   \
    do {                                                                    \
        u64 th = mul2((tv), W0);                                            \
        float tl, thh; upk(th, tl, thh);                                    \
        u64 s = pk(mufu_sin(tl), mufu_sin(thh));                            \
        u64 v = pk(mufu_cos(tl), mufu_cos(thh));                            \
        v = add2(v, v);                       /* v0 = 2cos */               \
        A1[0] = fma2((yn), s, A1[0]);                                       \
        A2[0] = fma2((yn), v, A2[0]);                                       \
        _Pragma("unroll")                                                   \
        for (int k = 1; k < NOCT; k++) {                                    \
            s = mul2(s, v);                                                 \
            v = fma2(v, v, NEG2);                                           \
            A1[k] = fma2((yn), s, A1[k]);                                   \
            A2[k] = fma2((yn), v, A2[k]);                                   \
        }                                                                   \
    } while (0)

// -------- single fused kernel --------
// block (f0, b): 64 threads = 2 warps, 16 packed time-pairs per thread.
// __launch_bounds__(64, 14): 14 blocks/SM * 148 SMs = 2072 >= 2048 blocks
// -> the entire grid is ONE wave (removes the 2-wave quantization at regs=80).
// Register budget 65536/(14*64) = 73; body compiled at 72 in R7, so no spills.
__global__ __launch_bounds__(64, 14) void spectral_kernel(const float* __restrict__ batch,
                                                          const float* __restrict__ freqs,
                                                          float* __restrict__ out) {
    const int f0  = blockIdx.x;
    const int b   = blockIdx.y;
    const int tid = threadIdx.x;
    const int lane = tid & 31, w = tid >> 5;

    __shared__ float sred[2][18];
    __shared__ float rstat[2][2];
    __shared__ float fmean_s, finv_s;
    __shared__ int   last_s;

    const float4* __restrict__ ts4 = (const float4*)(batch + b * (2 * T_LEN));
    const float4* __restrict__ ys4 = (const float4*)(batch + b * (2 * T_LEN) + T_LEN);

    // ---- slim prelude: block-redundant mean of y (std scale cancels in the
    //      final tnorm; EPS perturbation ~3e-7 relative) ----
    float msum = 0.0f;
#pragma unroll
    for (int i = 0; i < 8; i++) {
        float4 v = __ldg(&ys4[i * 64 + tid]);
        msum += (v.x + v.y) + (v.z + v.w);
    }
#pragma unroll
    for (int o = 16; o; o >>= 1) msum += __shfl_down_sync(0xffffffffu, msum, o);
    if (lane == 0) rstat[w][0] = msum;
    __syncthreads();
    const float m = (rstat[0][0] + rstat[1][0]) * (1.0f / T_LEN);
    const u64 M = pk(m, m);

    const float w0f = freqs[f0] * 6.283185307179586f;   // omega (radians)
    const u64 W0   = pk(w0f, w0f);
    const u64 NEG2 = bc2(-2.0f);

    u64 A1[NOCT], A2[NOCT];
#pragma unroll
    for (int k = 0; k < NOCT; k++) { A1[k] = 0; A2[k] = 0; }

    // ---- main loop: software-pipelined (1 iter lookahead) ----
    float4 t_n = __ldg(&ts4[tid]);
    float4 y_n = __ldg(&ys4[tid]);
#pragma unroll
    for (int i = 0; i < 8; i++) {
        float4 t4 = t_n, y4 = y_n;
        if (i < 7) {
            t_n = __ldg(&ts4[(i + 1) * 64 + tid]);
            y_n = __ldg(&ys4[(i + 1) * 64 + tid]);
        }
        u64 tvA = pk(t4.x, t4.y), ynA = sub2(pk(y4.x, y4.y), M);
        u64 tvB = pk(t4.z, t4.w), ynB = sub2(pk(y4.z, y4.w), M);
        EVAL_PAIR(tvA, ynA);
        EVAL_PAIR(tvB, ynB);
    }

    // ---- per-warp packed butterfly reduction ----
#pragma unroll
    for (int k = 0; k < NOCT; k++) {
#pragma unroll
        for (int o = 16; o; o >>= 1) {
            A1[k] = add2(A1[k], __shfl_down_sync(0xffffffffu, A1[k], o));
            A2[k] = add2(A2[k], __shfl_down_sync(0xffffffffu, A2[k], o));
        }
    }
    if (lane == 0) {
#pragma unroll
        for (int k = 0; k < NOCT; k++) {
            float lo, hi;
            upk(A1[k], lo, hi); sred[w][k]        = lo + hi;
            upk(A2[k], lo, hi); sred[w][NOCT + k] = lo + hi;
        }
    }
    __syncthreads();

    // ---- combine 2 warps, write magnitude (P2 carries factor 2 -> halve) ----
    if (tid < NOCT) {
        float P1 = sred[0][tid]        + sred[1][tid];
        float P2 = (sred[0][NOCT + tid] + sred[1][NOCT + tid]) * 0.5f;
        float mg = sqrtf(fmaf(P1, P1, P2 * P2));
        __stcg(&g_mag[b * NFREQ + tid * NF0 + f0], mg);
    }
    __threadfence();
    __syncthreads();
    if (tid == 0) last_s = (atomicAdd(&g_cnt[b], 1) == NF0 - 1);
    __syncthreads();
    if (!last_s) return;
    __threadfence();

    // ---- last block per batch: tnorm over 1152 freqs ----
    float mv[18];
    float sm = 0.0f, sq2 = 0.0f;
#pragma unroll
    for (int j = 0; j < 18; j++) {
        float v = __ldcg(&g_mag[b * NFREQ + j * 64 + tid]);
        mv[j] = v;
        sm += v;
        sq2 = fmaf(v, v, sq2);
    }
#pragma unroll
    for (int o = 16; o; o >>= 1) {
        sm  += __shfl_down_sync(0xffffffffu, sm, o);
        sq2 += __shfl_down_sync(0xffffffffu, sq2, o);
    }
    if (lane == 0) { rstat[w][0] = sm; rstat[w][1] = sq2; }
    __syncthreads();
    if (tid == 0) {
        float S = rstat[0][0] + rstat[1][0];
        float Q = rstat[0][1] + rstat[1][1];
        float mean = S * (1.0f / NFREQ);
        float var  = (Q - (float)NFREQ * mean * mean) * (1.0f / (NFREQ - 1));
        fmean_s = mean;
        finv_s  = 1.0f / (sqrtf(var) + 1e-4f);
        g_cnt[b] = 0;   // reset for next graph replay
    }
    __syncthreads();
    const float mmean = fmean_s, minv = finv_s;
#pragma unroll
    for (int j = 0; j < 18; j++)
        out[b * NFREQ + j * 64 + tid] = (mv[j] - mmean) * minv;
}

// -------- launch --------
extern "C" void kernel_launch(void* const* d_in, const int* in_sizes, int n_in,
                              void* d_out, int out_size) {
    const float* batch = (const float*)d_in[0];   // (16, 2, 2048) f32
    const float* freqs = (const float*)d_in[1];   // (1152,) f32
    float* out = (float*)d_out;                   // (16, 1, 1152) f32

    spectral_kernel<<<dim3(NF0, BATCH), 64>>>(batch, freqs, out);
}

// round 12
// speedup vs baseline: 1.1056x; 1.1056x over previous
#include <cuda_runtime.h>

#define T_LEN   2048
#define BATCH   16
#define NFREQ   1152
#define NOCT    9
#define NF0     128

typedef unsigned long long u64;

// -------- device scratch --------
__device__ float g_mag[BATCH * NFREQ];
__device__ int   g_cnt[BATCH];            // zero-init; self-resetting each launch

// -------- packed f32x2 helpers --------
__device__ __forceinline__ u64 pk(float lo, float hi) {
    u64 r; asm("mov.b64 %0,{%1,%2};" : "=l"(r) : "f"(lo), "f"(hi)); return r;
}
__device__ __forceinline__ void upk(u64 v, float& lo, float& hi) {
    asm("mov.b64 {%0,%1},%2;" : "=f"(lo), "=f"(hi) : "l"(v));
}
__device__ __forceinline__ u64 bc2(float v) {
    unsigned u = __float_as_uint(v);
    return (u64)u | ((u64)u << 32);
}
__device__ __forceinline__ u64 fma2(u64 a, u64 b, u64 c) {
    u64 d; asm("fma.rn.f32x2 %0,%1,%2,%3;" : "=l"(d) : "l"(a), "l"(b), "l"(c)); return d;
}
__device__ __forceinline__ u64 mul2(u64 a, u64 b) {
    u64 d; asm("mul.rn.f32x2 %0,%1,%2;" : "=l"(d) : "l"(a), "l"(b)); return d;
}
__device__ __forceinline__ u64 add2(u64 a, u64 b) {
    u64 d; asm("add.rn.f32x2 %0,%1,%2;" : "=l"(d) : "l"(a), "l"(b)); return d;
}
__device__ __forceinline__ u64 sub2(u64 a, u64 b) {
    u64 d; asm("sub.rn.f32x2 %0,%1,%2;" : "=l"(d) : "l"(a), "l"(b)); return d;
}
__device__ __forceinline__ float mufu_sin(float x) {
    float r; asm("sin.approx.f32 %0, %1;" : "=f"(r) : "f"(x)); return r;
}
__device__ __forceinline__ float mufu_cos(float x) {
    float r; asm("cos.approx.f32 %0, %1;" : "=f"(r) : "f"(x)); return r;
}

// One packed pair of time steps across 9 octaves, via TWO independent
// Chebyshev ladders seeded by MUFU at octave 0 and octave 5 (theta5 = 32*theta0).
// Halves the serial dependency chain (4 resp. 3 doubling steps instead of 8)
// and reduces error amplification from 2^8 to 2^4/2^3.
//   ladder: s' = s*v, v' = v*v - 2  with v = 2cos
// A2 accumulates yn*v == 2*(y*cos); factor 2 removed once in the epilogue.
#define EVAL_PAIR(tv, yn)                                                   \
    do {                                                                    \
        u64 th  = mul2((tv), W0);                                           \
        u64 th2 = mul2((tv), W5);                                           \
        float a0, b0, a5, b5;                                               \
        upk(th,  a0, b0);                                                   \
        upk(th2, a5, b5);                                                   \
        u64 s  = pk(mufu_sin(a0), mufu_sin(b0));                            \
        u64 v  = pk(mufu_cos(a0), mufu_cos(b0));                            \
        u64 s2 = pk(mufu_sin(a5), mufu_sin(b5));                            \
        u64 v2 = pk(mufu_cos(a5), mufu_cos(b5));                            \
        v  = add2(v, v);                                                    \
        v2 = add2(v2, v2);                                                  \
        A1[0] = fma2((yn), s,  A1[0]);                                      \
        A2[0] = fma2((yn), v,  A2[0]);                                      \
        A1[5] = fma2((yn), s2, A1[5]);                                      \
        A2[5] = fma2((yn), v2, A2[5]);                                      \
        _Pragma("unroll")                                                   \
        for (int k = 1; k < 5; k++) {                                       \
            s = mul2(s, v);                                                 \
            v = fma2(v, v, NEG2);                                           \
            A1[k] = fma2((yn), s, A1[k]);                                   \
            A2[k] = fma2((yn), v, A2[k]);                                   \
        }                                                                   \
        _Pragma("unroll")                                                   \
        for (int k = 6; k < NOCT; k++) {                                    \
            s2 = mul2(s2, v2);                                              \
            v2 = fma2(v2, v2, NEG2);                                        \
            A1[k] = fma2((yn), s2, A1[k]);                                  \
            A2[k] = fma2((yn), v2, A2[k]);                                  \
        }                                                                   \
    } while (0)

// -------- single fused kernel --------
// block (f0, b): 64 threads = 2 warps, 16 packed time-pairs per thread.
__global__ __launch_bounds__(64) void spectral_kernel(const float* __restrict__ batch,
                                                      const float* __restrict__ freqs,
                                                      float* __restrict__ out) {
    const int f0  = blockIdx.x;
    const int b   = blockIdx.y;
    const int tid = threadIdx.x;
    const int lane = tid & 31, w = tid >> 5;

    __shared__ float sred[2][18];
    __shared__ float rstat[2][2];
    __shared__ float fmean_s, finv_s;
    __shared__ int   last_s;

    const float4* __restrict__ ts4 = (const float4*)(batch + b * (2 * T_LEN));
    const float4* __restrict__ ys4 = (const float4*)(batch + b * (2 * T_LEN) + T_LEN);

    // ---- slim prelude: block-redundant mean of y (std scale cancels in the
    //      final tnorm; EPS perturbation ~3e-7 relative) ----
    float msum = 0.0f;
#pragma unroll
    for (int i = 0; i < 8; i++) {
        float4 v = __ldg(&ys4[i * 64 + tid]);
        msum += (v.x + v.y) + (v.z + v.w);
    }
#pragma unroll
    for (int o = 16; o; o >>= 1) msum += __shfl_down_sync(0xffffffffu, msum, o);
    if (lane == 0) rstat[w][0] = msum;
    __syncthreads();
    const float m = (rstat[0][0] + rstat[1][0]) * (1.0f / T_LEN);
    const u64 M = pk(m, m);

    const float w0f = freqs[f0] * 6.283185307179586f;   // omega (radians)
    const float w5f = w0f * 32.0f;                      // octave-5 omega
    const u64 W0   = pk(w0f, w0f);
    const u64 W5   = pk(w5f, w5f);
    const u64 NEG2 = bc2(-2.0f);

    u64 A1[NOCT], A2[NOCT];
#pragma unroll
    for (int k = 0; k < NOCT; k++) { A1[k] = 0; A2[k] = 0; }

    // ---- main loop: software-pipelined (1 iter lookahead) ----
    float4 t_n = __ldg(&ts4[tid]);
    float4 y_n = __ldg(&ys4[tid]);
#pragma unroll
    for (int i = 0; i < 8; i++) {
        float4 t4 = t_n, y4 = y_n;
        if (i < 7) {
            t_n = __ldg(&ts4[(i + 1) * 64 + tid]);
            y_n = __ldg(&ys4[(i + 1) * 64 + tid]);
        }
        u64 tvA = pk(t4.x, t4.y), ynA = sub2(pk(y4.x, y4.y), M);
        u64 tvB = pk(t4.z, t4.w), ynB = sub2(pk(y4.z, y4.w), M);
        EVAL_PAIR(tvA, ynA);
        EVAL_PAIR(tvB, ynB);
    }

    // ---- per-warp packed butterfly reduction ----
#pragma unroll
    for (int k = 0; k < NOCT; k++) {
#pragma unroll
        for (int o = 16; o; o >>= 1) {
            A1[k] = add2(A1[k], __shfl_down_sync(0xffffffffu, A1[k], o));
            A2[k] = add2(A2[k], __shfl_down_sync(0xffffffffu, A2[k], o));
        }
    }
    if (lane == 0) {
#pragma unroll
        for (int k = 0; k < NOCT; k++) {
            float lo, hi;
            upk(A1[k], lo, hi); sred[w][k]        = lo + hi;
            upk(A2[k], lo, hi); sred[w][NOCT + k] = lo + hi;
        }
    }
    __syncthreads();

    // ---- combine 2 warps, write magnitude (P2 carries factor 2 -> halve) ----
    if (tid < NOCT) {
        float P1 = sred[0][tid]        + sred[1][tid];
        float P2 = (sred[0][NOCT + tid] + sred[1][NOCT + tid]) * 0.5f;
        float mg = sqrtf(fmaf(P1, P1, P2 * P2));
        __stcg(&g_mag[b * NFREQ + tid * NF0 + f0], mg);
    }
    __threadfence();
    __syncthreads();
    if (tid == 0) last_s = (atomicAdd(&g_cnt[b], 1) == NF0 - 1);
    __syncthreads();
    if (!last_s) return;
    __threadfence();

    // ---- last block per batch: tnorm over 1152 freqs ----
    float mv[18];
    float sm = 0.0f, sq2 = 0.0f;
#pragma unroll
    for (int j = 0; j < 18; j++) {
        float v = __ldcg(&g_mag[b * NFREQ + j * 64 + tid]);
        mv[j] = v;
        sm += v;
        sq2 = fmaf(v, v, sq2);
    }
#pragma unroll
    for (int o = 16; o; o >>= 1) {
        sm  += __shfl_down_sync(0xffffffffu, sm, o);
        sq2 += __shfl_down_sync(0xffffffffu, sq2, o);
    }
    if (lane == 0) { rstat[w][0] = sm; rstat[w][1] = sq2; }
    __syncthreads();
    if (tid == 0) {
        float S = rstat[0][0] + rstat[1][0];
        float Q = rstat[0][1] + rstat[1][1];
        float mean = S * (1.0f / NFREQ);
        float var  = (Q - (float)NFREQ * mean * mean) * (1.0f / (NFREQ - 1));
        fmean_s = mean;
        finv_s  = 1.0f / (sqrtf(var) + 1e-4f);
        g_cnt[b] = 0;   // reset for next graph replay
    }
    __syncthreads();
    const float mmean = fmean_s, minv = finv_s;
#pragma unroll
    for (int j = 0; j < 18; j++)
        out[b * NFREQ + j * 64 + tid] = (mv[j] - mmean) * minv;
}

// -------- launch --------
extern "C" void kernel_launch(void* const* d_in, const int* in_sizes, int n_in,
                              void* d_out, int out_size) {
    const float* batch = (const float*)d_in[0];   // (16, 2, 2048) f32
    const float* freqs = (const float*)d_in[1];   // (1152,) f32
    float* out = (float*)d_out;                   // (16, 1, 1152) f32

    spectral_kernel<<<dim3(NF0, BATCH), 64>>>(batch, freqs, out);
}

// round 13
// speedup vs baseline: 1.1080x; 1.0022x over previous
#include <cuda_runtime.h>

#define T_LEN   2048
#define BATCH   16
#define NFREQ   1152
#define NOCT    9
#define NF0     128

typedef unsigned long long u64;

// -------- device scratch --------
__device__ float g_mag[BATCH * NFREQ];
__device__ int   g_cnt[BATCH];            // zero-init; self-resetting each launch

// -------- packed f32x2 helpers --------
__device__ __forceinline__ u64 pk(float lo, float hi) {
    u64 r; asm("mov.b64 %0,{%1,%2};" : "=l"(r) : "f"(lo), "f"(hi)); return r;
}
__device__ __forceinline__ void upk(u64 v, float& lo, float& hi) {
    asm("mov.b64 {%0,%1},%2;" : "=f"(lo), "=f"(hi) : "l"(v));
}
__device__ __forceinline__ u64 bc2(float v) {
    unsigned u = __float_as_uint(v);
    return (u64)u | ((u64)u << 32);
}
__device__ __forceinline__ u64 fma2(u64 a, u64 b, u64 c) {
    u64 d; asm("fma.rn.f32x2 %0,%1,%2,%3;" : "=l"(d) : "l"(a), "l"(b), "l"(c)); return d;
}
__device__ __forceinline__ u64 mul2(u64 a, u64 b) {
    u64 d; asm("mul.rn.f32x2 %0,%1,%2;" : "=l"(d) : "l"(a), "l"(b)); return d;
}
__device__ __forceinline__ u64 add2(u64 a, u64 b) {
    u64 d; asm("add.rn.f32x2 %0,%1,%2;" : "=l"(d) : "l"(a), "l"(b)); return d;
}
__device__ __forceinline__ u64 sub2(u64 a, u64 b) {
    u64 d; asm("sub.rn.f32x2 %0,%1,%2;" : "=l"(d) : "l"(a), "l"(b)); return d;
}
__device__ __forceinline__ float mufu_sin(float x) {
    float r; asm("sin.approx.f32 %0, %1;" : "=f"(r) : "f"(x)); return r;
}
__device__ __forceinline__ float mufu_cos(float x) {
    float r; asm("cos.approx.f32 %0, %1;" : "=f"(r) : "f"(x)); return r;
}

// One packed pair of time steps across 9 octaves, via TWO independent
// Chebyshev ladders seeded by MUFU at octave 0 and octave 5 (theta5 = 32*theta0).
//   ladder: s' = s*v, v' = v*v - 2  with v = 2cos
// A2 accumulates yn*v == 2*(y*cos); factor 2 removed once in the epilogue.
#define EVAL_PAIR(tv, yn)                                                   \
    do {                                                                    \
        u64 th  = mul2((tv), W0);                                           \
        u64 th2 = mul2((tv), W5);                                           \
        float a0, b0, a5, b5;                                               \
        upk(th,  a0, b0);                                                   \
        upk(th2, a5, b5);                                                   \
        u64 s  = pk(mufu_sin(a0), mufu_sin(b0));                            \
        u64 v  = pk(mufu_cos(a0), mufu_cos(b0));                            \
        u64 s2 = pk(mufu_sin(a5), mufu_sin(b5));                            \
        u64 v2 = pk(mufu_cos(a5), mufu_cos(b5));                            \
        v  = add2(v, v);                                                    \
        v2 = add2(v2, v2);                                                  \
        A1[0] = fma2((yn), s,  A1[0]);                                      \
        A2[0] = fma2((yn), v,  A2[0]);                                      \
        A1[5] = fma2((yn), s2, A1[5]);                                      \
        A2[5] = fma2((yn), v2, A2[5]);                                      \
        _Pragma("unroll")                                                   \
        for (int k = 1; k < 5; k++) {                                       \
            s = mul2(s, v);                                                 \
            v = fma2(v, v, NEG2);                                           \
            A1[k] = fma2((yn), s, A1[k]);                                   \
            A2[k] = fma2((yn), v, A2[k]);                                   \
        }                                                                   \
        _Pragma("unroll")                                                   \
        for (int k = 6; k < NOCT; k++) {                                    \
            s2 = mul2(s2, v2);                                              \
            v2 = fma2(v2, v2, NEG2);                                        \
            A1[k] = fma2((yn), s2, A1[k]);                                  \
            A2[k] = fma2((yn), v2, A2[k]);                                  \
        }                                                                   \
    } while (0)

// -------- single fused kernel --------
// block (f0, b): 64 threads = 2 warps, 16 packed time-pairs per thread.
__global__ __launch_bounds__(64) void spectral_kernel(const float* __restrict__ batch,
                                                      const float* __restrict__ freqs,
                                                      float* __restrict__ out) {
    const int f0  = blockIdx.x;
    const int b   = blockIdx.y;
    const int tid = threadIdx.x;
    const int lane = tid & 31, w = tid >> 5;

    __shared__ float sred[2][18];
    __shared__ float rstat[2][2];
    __shared__ float fmean_s, finv_s;
    __shared__ int   last_s;

    const float4* __restrict__ ts4 = (const float4*)(batch + b * (2 * T_LEN));
    const float4* __restrict__ ys4 = (const float4*)(batch + b * (2 * T_LEN) + T_LEN);

    // ---- slim prelude: block-redundant mean of y (std scale cancels in the
    //      final tnorm; EPS perturbation ~3e-7 relative) ----
    float msum = 0.0f;
#pragma unroll
    for (int i = 0; i < 8; i++) {
        float4 v = __ldg(&ys4[i * 64 + tid]);
        msum += (v.x + v.y) + (v.z + v.w);
    }
#pragma unroll
    for (int o = 16; o; o >>= 1) msum += __shfl_down_sync(0xffffffffu, msum, o);
    if (lane == 0) rstat[w][0] = msum;
    __syncthreads();
    const float m = (rstat[0][0] + rstat[1][0]) * (1.0f / T_LEN);
    const u64 M = pk(m, m);

    const float w0f = freqs[f0] * 6.283185307179586f;   // omega (radians)
    const float w5f = w0f * 32.0f;                      // octave-5 omega
    const u64 W0   = pk(w0f, w0f);
    const u64 W5   = pk(w5f, w5f);
    const u64 NEG2 = bc2(-2.0f);

    u64 A1[NOCT], A2[NOCT];
#pragma unroll
    for (int k = 0; k < NOCT; k++) { A1[k] = 0; A2[k] = 0; }

    // ---- main loop: software-pipelined (1 iter lookahead) ----
    float4 t_n = __ldg(&ts4[tid]);
    float4 y_n = __ldg(&ys4[tid]);
#pragma unroll
    for (int i = 0; i < 8; i++) {
        float4 t4 = t_n, y4 = y_n;
        if (i < 7) {
            t_n = __ldg(&ts4[(i + 1) * 64 + tid]);
            y_n = __ldg(&ys4[(i + 1) * 64 + tid]);
        }
        u64 tvA = pk(t4.x, t4.y), ynA = sub2(pk(y4.x, y4.y), M);
        u64 tvB = pk(t4.z, t4.w), ynB = sub2(pk(y4.z, y4.w), M);
        EVAL_PAIR(tvA, ynA);
        EVAL_PAIR(tvB, ynB);
    }

    // ---- fold packed -> scalar FIRST (halves the SHFL count), then
    //      5-stage scalar butterfly: 90 SHFL instead of 180 ----
    float p[18];
#pragma unroll
    for (int k = 0; k < NOCT; k++) {
        float lo, hi;
        upk(A1[k], lo, hi); p[k]        = lo + hi;
        upk(A2[k], lo, hi); p[NOCT + k] = lo + hi;
    }
#pragma unroll
    for (int j = 0; j < 18; j++) {
#pragma unroll
        for (int o = 16; o; o >>= 1)
            p[j] += __shfl_down_sync(0xffffffffu, p[j], o);
    }
    if (lane == 0) {
#pragma unroll
        for (int j = 0; j < 18; j++) sred[w][j] = p[j];
    }
    __syncthreads();

    // ---- combine 2 warps, write magnitude (P2 carries factor 2 -> halve) ----
    if (tid < NOCT) {
        float P1 = sred[0][tid]        + sred[1][tid];
        float P2 = (sred[0][NOCT + tid] + sred[1][NOCT + tid]) * 0.5f;
        float mg = sqrtf(fmaf(P1, P1, P2 * P2));
        __stcg(&g_mag[b * NFREQ + tid * NF0 + f0], mg);
    }
    __threadfence();
    __syncthreads();
    if (tid == 0) last_s = (atomicAdd(&g_cnt[b], 1) == NF0 - 1);
    __syncthreads();
    if (!last_s) return;
    __threadfence();

    // ---- last block per batch: tnorm over 1152 freqs ----
    float mv[18];
    float sm = 0.0f, sq2 = 0.0f;
#pragma unroll
    for (int j = 0; j < 18; j++) {
        float v = __ldcg(&g_mag[b * NFREQ + j * 64 + tid]);
        mv[j] = v;
        sm += v;
        sq2 = fmaf(v, v, sq2);
    }
#pragma unroll
    for (int o = 16; o; o >>= 1) {
        sm  += __shfl_down_sync(0xffffffffu, sm, o);
        sq2 += __shfl_down_sync(0xffffffffu, sq2, o);
    }
    if (lane == 0) { rstat[w][0] = sm; rstat[w][1] = sq2; }
    __syncthreads();
    if (tid == 0) {
        float S = rstat[0][0] + rstat[1][0];
        float Q = rstat[0][1] + rstat[1][1];
        float mean = S * (1.0f / NFREQ);
        float var  = (Q - (float)NFREQ * mean * mean) * (1.0f / (NFREQ - 1));
        fmean_s = mean;
        finv_s  = 1.0f / (sqrtf(var) + 1e-4f);
        g_cnt[b] = 0;   // reset for next graph replay
    }
    __syncthreads();
    const float mmean = fmean_s, minv = finv_s;
#pragma unroll
    for (int j = 0; j < 18; j++)
        out[b * NFREQ + j * 64 + tid] = (mv[j] - mmean) * minv;
}

// -------- launch --------
extern "C" void kernel_launch(void* const* d_in, const int* in_sizes, int n_in,
                              void* d_out, int out_size) {
    const float* batch = (const float*)d_in[0];   // (16, 2, 2048) f32
    const float* freqs = (const float*)d_in[1];   // (1152,) f32
    float* out = (float*)d_out;                   // (16, 1, 1152) f32

    spectral_kernel<<<dim3(NF0, BATCH), 64>>>(batch, freqs, out);
}